// round 4
// baseline (speedup 1.0000x reference)
#include <cuda_runtime.h>

// ============================================================================
// LightningIndexer fused kernel for GB300 (sm_103a)
//
// out[b,q,k] = sum_h w[b,q,h] * relu(scale * dot(q[b,q,h,:], k[b,k,:])) + bias
//   q,w from query_tokens @ Wq (scale folded into q)
//   k from key_tokens @ Wk + additive 2D sinusoidal pos-emb
//
// Strategy: packed f32x2 FMA throughout (2 fp32 FLOP per FMA-pipe issue).
//   - keys stored pair-interleaved: kp[pair][d] = {k[2p][d], k[2p+1][d]}
//   - q data stored duplicated: qd[row][slot] = {v, v}  (18 slots: h0 d0-7,
//     h1 d0-7, w0, w1)
// ============================================================================

#define ULL unsigned long long

__device__ __forceinline__ ULL pack2(float lo, float hi) {
    ULL r; asm("mov.b64 %0, {%1,%2};" : "=l"(r) : "f"(lo), "f"(hi)); return r;
}
__device__ __forceinline__ float2 unpack2(ULL v) {
    float2 f; asm("mov.b64 {%0,%1}, %2;" : "=f"(f.x), "=f"(f.y) : "l"(v)); return f;
}
__device__ __forceinline__ ULL fma2(ULL a, ULL b, ULL c) {
    ULL d; asm("fma.rn.f32x2 %0, %1, %2, %3;" : "=l"(d) : "l"(a), "l"(b), "l"(c)); return d;
}
__device__ __forceinline__ ULL add2(ULL a, ULL b) {
    ULL d; asm("add.rn.f32x2 %0, %1, %2;" : "=l"(d) : "l"(a), "l"(b)); return d;
}

constexpr int B   = 2;
constexpr int N   = 4096;
constexpr int DIM = 768;
constexpr int CQ  = 18;   // Wq output cols = H*(KD+1)
constexpr int CK  = 8;    // Wk output cols = KD
constexpr float SCALE = 0.35355339059327373f;  // 8^-0.5

// Scores kernel tiling
constexpr int QT  = 32;           // queries per block
constexpr int TPB = 256;          // threads per block
constexpr int KPT = 8;            // keys per thread
constexpr int KTB = TPB * KPT;    // 2048 keys per block

// Scratch (device globals: no allocation allowed)
__device__ __align__(16) float  g_WqT[CQ * DIM];          // transposed Wq
__device__ __align__(16) float  g_WkT[CK * DIM];          // transposed Wk
__device__ __align__(16) float2 g_qd[(size_t)B * N * 18]; // duplicated q/w data
__device__ __align__(16) float2 g_kp[(size_t)(B * N / 2) * 8]; // pair-packed keys

// Robustly decode a positive integer scalar that may be stored as
// int32 / low-word-of-int64 / float32 on device.
__device__ __forceinline__ int decode_dim(const void* p) {
    int vi = *(const int*)p;
    if (vi > 0 && vi < 100000) return vi;
    float vf = __int_as_float(vi);
    int r = (int)vf;
    return (r > 0 && r < 100000) ? r : 1;
}

// ---------------------------------------------------------------------------
// Kernel 0: transpose the tiny weight matrices so projection lanes read
// coalesced columns (1 L1 line per warp LDG instead of 18).
// ---------------------------------------------------------------------------
__global__ void transpose_w_kernel(const float* __restrict__ Wq,
                                   const float* __restrict__ Wk) {
    int t = blockIdx.x * blockDim.x + threadIdx.x;
    if (t < DIM * CQ) {
        int k = t / CQ, c = t % CQ;
        g_WqT[c * DIM + k] = Wq[t];
    }
    if (t < DIM * CK) {
        int k = t / CK, c = t % CK;
        g_WkT[c * DIM + k] = Wk[t];
    }
}

// ---------------------------------------------------------------------------
// Kernel 1: q/w projection. Warp handles 4 rows as 2 f32x2 row-pairs,
// lanes split K (768), shuffle-reduce to lane 0, write duplicated layout.
// Slot map: col 0-7 -> slot 0-7 (h0 dims, *SCALE); col 8 -> slot 16 (w0);
//           col 9-16 -> slot 8-15 (h1 dims, *SCALE); col 17 -> slot 17 (w1)
// ---------------------------------------------------------------------------
__global__ void __launch_bounds__(256) proj_q_kernel(const float* __restrict__ tok) {
    int warp = threadIdx.x >> 5, lane = threadIdx.x & 31;
    int r0 = blockIdx.x * 32 + warp * 4;
    const float* x = tok + (size_t)r0 * DIM;

    ULL acc0[CQ], acc1[CQ];
#pragma unroll
    for (int c = 0; c < CQ; c++) { acc0[c] = 0ull; acc1[c] = 0ull; }

#pragma unroll 2
    for (int i = 0; i < DIM / 32; i++) {
        int k = lane + i * 32;
        ULL x01 = pack2(x[k], x[DIM + k]);
        ULL x23 = pack2(x[2 * DIM + k], x[3 * DIM + k]);
#pragma unroll
        for (int c = 0; c < CQ; c++) {
            float wv = g_WqT[c * DIM + k];
            ULL wd = pack2(wv, wv);
            acc0[c] = fma2(x01, wd, acc0[c]);
            acc1[c] = fma2(x23, wd, acc1[c]);
        }
    }
#pragma unroll
    for (int c = 0; c < CQ; c++) {
#pragma unroll
        for (int m = 16; m >= 1; m >>= 1) {
            acc0[c] = add2(acc0[c], __shfl_down_sync(0xffffffffu, acc0[c], m));
            acc1[c] = add2(acc1[c], __shfl_down_sync(0xffffffffu, acc1[c], m));
        }
    }
    if (lane == 0) {
#pragma unroll
        for (int c = 0; c < CQ; c++) {
            int slot; float mul;
            if (c < 8)       { slot = c;      mul = SCALE; }
            else if (c == 8) { slot = 16;     mul = 1.0f; }
            else if (c < 17) { slot = c - 1;  mul = SCALE; }
            else             { slot = 17;     mul = 1.0f; }
            float2 v0 = unpack2(acc0[c]);
            float2 v1 = unpack2(acc1[c]);
            float a = v0.x * mul, b = v0.y * mul, cc2 = v1.x * mul, d = v1.y * mul;
            g_qd[(size_t)(r0 + 0) * 18 + slot] = make_float2(a, a);
            g_qd[(size_t)(r0 + 1) * 18 + slot] = make_float2(b, b);
            g_qd[(size_t)(r0 + 2) * 18 + slot] = make_float2(cc2, cc2);
            g_qd[(size_t)(r0 + 3) * 18 + slot] = make_float2(d, d);
        }
    }
}

// ---------------------------------------------------------------------------
// Additive 2D sinusoidal position embedding value for (token n, dim d).
// d_half = 4; per axis: [sin(a0), cos(a0), sin(a1), cos(a1)],
// a_j = (coord / max(extent-1,1)) * freq_j * extent;
// freq = {1, exp(-2*ln(1e4)/4)} ~= {1, 0.01}
// ---------------------------------------------------------------------------
__device__ __forceinline__ float pos_val(int n, int d, int h, int w) {
    int dd = d & 3;
    float t, sc;
    if (d < 4) {
        int y = n / w;
        int hm1 = (h - 1 > 1) ? (h - 1) : 1;
        t = (float)y / (float)hm1; sc = (float)h;
    } else {
        int xx = n % w;
        int wm1 = (w - 1 > 1) ? (w - 1) : 1;
        t = (float)xx / (float)wm1; sc = (float)w;
    }
    float fr = (dd < 2) ? 1.0f : expf(-0.5f * logf(10000.0f));
    float a = (t * fr) * sc;
    return (dd & 1) ? cosf(a) : sinf(a);
}

// ---------------------------------------------------------------------------
// Kernel 2: k projection + pos-emb, written pair-interleaved:
// kp[pair p][d] = { k[2p][d], k[2p+1][d] }
// ---------------------------------------------------------------------------
__global__ void __launch_bounds__(256) proj_k_kernel(const float* __restrict__ tok,
                                                     const void* __restrict__ hptr,
                                                     const void* __restrict__ wptr) {
    int warp = threadIdx.x >> 5, lane = threadIdx.x & 31;
    int r0 = blockIdx.x * 32 + warp * 4;
    const float* x = tok + (size_t)r0 * DIM;

    ULL acc0[CK], acc1[CK];
#pragma unroll
    for (int c = 0; c < CK; c++) { acc0[c] = 0ull; acc1[c] = 0ull; }

#pragma unroll 2
    for (int i = 0; i < DIM / 32; i++) {
        int k = lane + i * 32;
        ULL x01 = pack2(x[k], x[DIM + k]);
        ULL x23 = pack2(x[2 * DIM + k], x[3 * DIM + k]);
#pragma unroll
        for (int c = 0; c < CK; c++) {
            float wv = g_WkT[c * DIM + k];
            ULL wd = pack2(wv, wv);
            acc0[c] = fma2(x01, wd, acc0[c]);
            acc1[c] = fma2(x23, wd, acc1[c]);
        }
    }
#pragma unroll
    for (int c = 0; c < CK; c++) {
#pragma unroll
        for (int m = 16; m >= 1; m >>= 1) {
            acc0[c] = add2(acc0[c], __shfl_down_sync(0xffffffffu, acc0[c], m));
            acc1[c] = add2(acc1[c], __shfl_down_sync(0xffffffffu, acc1[c], m));
        }
    }
    if (lane == 0) {
        int h = decode_dim(hptr);
        int w = decode_dim(wptr);
        int p = r0 >> 1;
#pragma unroll
        for (int c = 0; c < CK; c++) {
            float2 v0 = unpack2(acc0[c]);
            float2 v1 = unpack2(acc1[c]);
            float a0 = v0.x + pos_val((r0 + 0) & (N - 1), c, h, w);
            float a1 = v0.y + pos_val((r0 + 1) & (N - 1), c, h, w);
            float a2 = v1.x + pos_val((r0 + 2) & (N - 1), c, h, w);
            float a3 = v1.y + pos_val((r0 + 3) & (N - 1), c, h, w);
            g_kp[(size_t)(p + 0) * 8 + c] = make_float2(a0, a1);
            g_kp[(size_t)(p + 1) * 8 + c] = make_float2(a2, a3);
        }
    }
}

// ---------------------------------------------------------------------------
// Kernel 3: fused scores. Block = 32 queries x 2048 keys; thread owns 8
// consecutive keys (4 f32x2 pairs, kept in registers across the q loop).
// q data broadcast-loaded from global (same address across the block -> 1
// sector per warp, L1/L2 hot).
// Per q-iter per thread: 64 FFMA2 (dots) + 16 FMNMX (relu) + 16 FFMA
// (w-combine + bias) + 2 STG.128 -> FMA-pipe bound ~0.94 outputs/cyc/SM.
// ---------------------------------------------------------------------------
__global__ void __launch_bounds__(256) scores_kernel(const float* __restrict__ sb,
                                                     float* __restrict__ out) {
    int b = blockIdx.z;
    int q0 = blockIdx.y * QT;
    int tid = threadIdx.x;
    size_t kbase = (size_t)blockIdx.x * KTB + (size_t)tid * KPT;

    // Load this thread's 4 key pairs (8 keys x 8 dims) into registers.
    ULL kreg[4][8];
    const ULL* kp = (const ULL*)(g_kp +
        ((size_t)b * (N / 2) + (size_t)blockIdx.x * (KTB / 2) + tid * 4) * 8);
#pragma unroll
    for (int pp = 0; pp < 4; pp++)
#pragma unroll
        for (int d = 0; d < 8; d++)
            kreg[pp][d] = kp[pp * 8 + d];

    float bias = sb[0];
    const ULL* qv = (const ULL*)(g_qd + ((size_t)b * N + q0) * 18);
    float* orow = out + ((size_t)b * N + q0) * N + kbase;

    for (int q = 0; q < QT; q++) {
        ULL acc0[4], acc1[4];
#pragma unroll
        for (int pp = 0; pp < 4; pp++) { acc0[pp] = 0ull; acc1[pp] = 0ull; }
#pragma unroll
        for (int d = 0; d < 8; d++) {
            ULL qa = qv[d];      // head 0, dim d, duplicated {v,v}
            ULL qb = qv[8 + d];  // head 1
#pragma unroll
            for (int pp = 0; pp < 4; pp++) {
                acc0[pp] = fma2(kreg[pp][d], qa, acc0[pp]);
                acc1[pp] = fma2(kreg[pp][d], qb, acc1[pp]);
            }
        }
        const float* qf = (const float*)qv;
        float w0 = qf[32];  // slot 16 .x
        float w1 = qf[34];  // slot 17 .x
        float o[8];
#pragma unroll
        for (int pp = 0; pp < 4; pp++) {
            float2 a0 = unpack2(acc0[pp]);
            float2 a1 = unpack2(acc1[pp]);
            float t0 = fmaf(w0, fmaxf(a0.x, 0.f), bias);
            float t1 = fmaf(w0, fmaxf(a0.y, 0.f), bias);
            o[2 * pp]     = fmaf(w1, fmaxf(a1.x, 0.f), t0);
            o[2 * pp + 1] = fmaf(w1, fmaxf(a1.y, 0.f), t1);
        }
        float4* o4 = (float4*)orow;
        o4[0] = make_float4(o[0], o[1], o[2], o[3]);
        o4[1] = make_float4(o[4], o[5], o[6], o[7]);
        qv += 18;
        orow += N;
    }
}

// ---------------------------------------------------------------------------
extern "C" void kernel_launch(void* const* d_in, const int* in_sizes, int n_in,
                              void* d_out, int out_size) {
    const float* qt = (const float*)d_in[0];  // query_tokens (B,N,768)
    const float* kt = (const float*)d_in[1];  // key_tokens   (B,N,768)
    const float* Wq = (const float*)d_in[2];  // (768,18)
    const float* Wk = (const float*)d_in[3];  // (768,8)
    const float* sb = (const float*)d_in[4];  // spatial_bias (1,1,1)
    const void*  hp = d_in[5];                // height (scalar)
    const void*  wp = d_in[6];                // width  (scalar)
    float* out = (float*)d_out;               // (B,N,N) fp32
    (void)in_sizes; (void)n_in; (void)out_size;

    transpose_w_kernel<<<(DIM * CQ + 255) / 256, 256>>>(Wq, Wk);
    proj_q_kernel<<<(B * N) / 32, 256>>>(qt);
    proj_k_kernel<<<(B * N) / 32, 256>>>(kt, hp, wp);

    dim3 grid(N / KTB, N / QT, B);  // (2, 128, 2)
    scores_kernel<<<grid, TPB>>>(sb, out);
}

// round 14
// speedup vs baseline: 1.1625x; 1.1625x over previous
#include <cuda_runtime.h>

// ============================================================================
// LightningIndexer fused kernel for GB300 (sm_103a)  — Round 14 (R5 design,
// resubmitted unchanged: rounds 5-13 all died to broker infra failures before
// execution; this design has never been measured).
//
// out[b,q,k] = sum_h w[b,q,h] * relu(scale * dot(q[b,q,h,:], k[b,k,:])) + bias
//
// R4 profile: scores 56us latency-bound (occ 21.8%, issue 25%, 126 regs);
// prep kernels ~49us. This design: KPT=4 + 3 CTAs/SM + LDG.128 q loads +
// packed epilogue + streaming stores; float4-based projections.
// ============================================================================

#define ULL unsigned long long

__device__ __forceinline__ ULL pack2(float lo, float hi) {
    ULL r; asm("mov.b64 %0, {%1,%2};" : "=l"(r) : "f"(lo), "f"(hi)); return r;
}
__device__ __forceinline__ float2 unpack2(ULL v) {
    float2 f; asm("mov.b64 {%0,%1}, %2;" : "=f"(f.x), "=f"(f.y) : "l"(v)); return f;
}
__device__ __forceinline__ ULL fma2(ULL a, ULL b, ULL c) {
    ULL d; asm("fma.rn.f32x2 %0, %1, %2, %3;" : "=l"(d) : "l"(a), "l"(b), "l"(c)); return d;
}
__device__ __forceinline__ ULL add2(ULL a, ULL b) {
    ULL d; asm("add.rn.f32x2 %0, %1, %2;" : "=l"(d) : "l"(a), "l"(b)); return d;
}

constexpr int B   = 2;
constexpr int N   = 4096;
constexpr int DIM = 768;
constexpr int CQ  = 18;   // Wq output cols = H*(KD+1)
constexpr int CK  = 8;    // Wk output cols = KD
constexpr float SCALE = 0.35355339059327373f;  // 8^-0.5

// Scores tiling
constexpr int QT  = 32;           // queries per block
constexpr int TPB = 256;          // threads per block
constexpr int KPT = 4;            // keys per thread (2 f32x2 pairs)
constexpr int KTB = TPB * KPT;    // 1024 keys per block

// Scratch (device globals: no allocation allowed)
__device__ __align__(16) float  g_WqT[CQ * DIM];               // transposed Wq
__device__ __align__(16) float  g_WkT[CK * DIM];               // transposed Wk
__device__ __align__(16) float2 g_qd[(size_t)B * N * 18];      // duplicated q/w
__device__ __align__(16) float2 g_kp[(size_t)(B * N / 2) * 8]; // pair-packed k

// Robust positive-int scalar decode (int32 / int64-low-word / float32).
__device__ __forceinline__ int decode_dim(const void* p) {
    int vi = *(const int*)p;
    if (vi > 0 && vi < 100000) return vi;
    float vf = __int_as_float(vi);
    int r = (int)vf;
    return (r > 0 && r < 100000) ? r : 1;
}

// ---------------------------------------------------------------------------
// Kernel 0: transpose the tiny weight matrices (coalesced column reads later).
// ---------------------------------------------------------------------------
__global__ void transpose_w_kernel(const float* __restrict__ Wq,
                                   const float* __restrict__ Wk) {
    int t = blockIdx.x * blockDim.x + threadIdx.x;
    if (t < DIM * CQ) {
        int k = t / CQ, c = t % CQ;
        g_WqT[c * DIM + k] = Wq[t];
    }
    if (t < DIM * CK) {
        int k = t / CK, c = t % CK;
        g_WkT[c * DIM + k] = Wk[t];
    }
}

// ---------------------------------------------------------------------------
// Kernel 1: q/w projection. Warp = 4 rows x 9 cols (half of 18); two warps
// per row-group. 6 iterations of float4 loads (lane covers 4 consecutive k).
// Row-pairs packed as f32x2. Shuffle-reduce, lane 0 writes duplicated layout.
// Col map: c'<8 -> slot c' (*SCALE); c'==8 -> slot 16; c'<17 -> slot c'-1
// (*SCALE); c'==17 -> slot 17.
// ---------------------------------------------------------------------------
__global__ void __launch_bounds__(256, 3) proj_q_kernel(const float* __restrict__ tok) {
    int warp = threadIdx.x >> 5, lane = threadIdx.x & 31;
    int rg   = warp >> 1;          // row group 0..3
    int half = warp & 1;           // column half
    int r0   = blockIdx.x * 16 + rg * 4;
    int cbase = half * 9;

    const float4* x4 = (const float4*)(tok + (size_t)r0 * DIM);  // row stride 192
    const float4* w4 = (const float4*)g_WqT;                      // row stride 192

    ULL acc[9][2];
#pragma unroll
    for (int c = 0; c < 9; c++) { acc[c][0] = 0ull; acc[c][1] = 0ull; }

#pragma unroll
    for (int i = 0; i < 6; i++) {
        int kk = lane + i * 32;  // float4 index within row
        float4 xr0 = x4[0 * 192 + kk];
        float4 xr1 = x4[1 * 192 + kk];
        float4 xr2 = x4[2 * 192 + kk];
        float4 xr3 = x4[3 * 192 + kk];
        ULL xp0[4], xp1[4];
        xp0[0] = pack2(xr0.x, xr1.x); xp1[0] = pack2(xr2.x, xr3.x);
        xp0[1] = pack2(xr0.y, xr1.y); xp1[1] = pack2(xr2.y, xr3.y);
        xp0[2] = pack2(xr0.z, xr1.z); xp1[2] = pack2(xr2.z, xr3.z);
        xp0[3] = pack2(xr0.w, xr1.w); xp1[3] = pack2(xr2.w, xr3.w);
#pragma unroll
        for (int c = 0; c < 9; c++) {
            float4 wv = w4[(size_t)(cbase + c) * 192 + kk];
            ULL wd;
            wd = pack2(wv.x, wv.x);
            acc[c][0] = fma2(xp0[0], wd, acc[c][0]);
            acc[c][1] = fma2(xp1[0], wd, acc[c][1]);
            wd = pack2(wv.y, wv.y);
            acc[c][0] = fma2(xp0[1], wd, acc[c][0]);
            acc[c][1] = fma2(xp1[1], wd, acc[c][1]);
            wd = pack2(wv.z, wv.z);
            acc[c][0] = fma2(xp0[2], wd, acc[c][0]);
            acc[c][1] = fma2(xp1[2], wd, acc[c][1]);
            wd = pack2(wv.w, wv.w);
            acc[c][0] = fma2(xp0[3], wd, acc[c][0]);
            acc[c][1] = fma2(xp1[3], wd, acc[c][1]);
        }
    }
#pragma unroll
    for (int c = 0; c < 9; c++) {
#pragma unroll
        for (int m = 16; m >= 1; m >>= 1) {
            acc[c][0] = add2(acc[c][0], __shfl_down_sync(0xffffffffu, acc[c][0], m));
            acc[c][1] = add2(acc[c][1], __shfl_down_sync(0xffffffffu, acc[c][1], m));
        }
    }
    if (lane == 0) {
#pragma unroll
        for (int c = 0; c < 9; c++) {
            int cc = cbase + c;
            int slot; float mul;
            if (cc < 8)       { slot = cc;     mul = SCALE; }
            else if (cc == 8) { slot = 16;     mul = 1.0f; }
            else if (cc < 17) { slot = cc - 1; mul = SCALE; }
            else              { slot = 17;     mul = 1.0f; }
            float2 v0 = unpack2(acc[c][0]);
            float2 v1 = unpack2(acc[c][1]);
            float a = v0.x * mul, b = v0.y * mul, e = v1.x * mul, d = v1.y * mul;
            g_qd[(size_t)(r0 + 0) * 18 + slot] = make_float2(a, a);
            g_qd[(size_t)(r0 + 1) * 18 + slot] = make_float2(b, b);
            g_qd[(size_t)(r0 + 2) * 18 + slot] = make_float2(e, e);
            g_qd[(size_t)(r0 + 3) * 18 + slot] = make_float2(d, d);
        }
    }
}

// ---------------------------------------------------------------------------
// 2D sinusoidal position embedding value for (token n, dim d).
// freq = {1, exp(-2 ln(1e4)/4)}; per axis [sin a0, cos a0, sin a1, cos a1].
// ---------------------------------------------------------------------------
__device__ __forceinline__ float pos_val(int n, int d, int h, int w) {
    int dd = d & 3;
    float t, sc;
    if (d < 4) {
        int y = n / w;
        int hm1 = (h - 1 > 1) ? (h - 1) : 1;
        t = (float)y / (float)hm1; sc = (float)h;
    } else {
        int xx = n % w;
        int wm1 = (w - 1 > 1) ? (w - 1) : 1;
        t = (float)xx / (float)wm1; sc = (float)w;
    }
    float fr = (dd < 2) ? 1.0f : expf(-0.5f * logf(10000.0f));
    float a = (t * fr) * sc;
    return (dd & 1) ? cosf(a) : sinf(a);
}

// ---------------------------------------------------------------------------
// Kernel 2: k projection + pos-emb. Warp = 4 rows x 8 cols, float4 loads.
// Row-pair accumulators match g_kp layout directly.
// ---------------------------------------------------------------------------
__global__ void __launch_bounds__(256, 3) proj_k_kernel(const float* __restrict__ tok,
                                                        const void* __restrict__ hptr,
                                                        const void* __restrict__ wptr) {
    int warp = threadIdx.x >> 5, lane = threadIdx.x & 31;
    int r0 = blockIdx.x * 32 + warp * 4;

    const float4* x4 = (const float4*)(tok + (size_t)r0 * DIM);
    const float4* w4 = (const float4*)g_WkT;

    ULL acc[8][2];
#pragma unroll
    for (int c = 0; c < 8; c++) { acc[c][0] = 0ull; acc[c][1] = 0ull; }

#pragma unroll
    for (int i = 0; i < 6; i++) {
        int kk = lane + i * 32;
        float4 xr0 = x4[0 * 192 + kk];
        float4 xr1 = x4[1 * 192 + kk];
        float4 xr2 = x4[2 * 192 + kk];
        float4 xr3 = x4[3 * 192 + kk];
        ULL xp0[4], xp1[4];
        xp0[0] = pack2(xr0.x, xr1.x); xp1[0] = pack2(xr2.x, xr3.x);
        xp0[1] = pack2(xr0.y, xr1.y); xp1[1] = pack2(xr2.y, xr3.y);
        xp0[2] = pack2(xr0.z, xr1.z); xp1[2] = pack2(xr2.z, xr3.z);
        xp0[3] = pack2(xr0.w, xr1.w); xp1[3] = pack2(xr2.w, xr3.w);
#pragma unroll
        for (int c = 0; c < 8; c++) {
            float4 wv = w4[(size_t)c * 192 + kk];
            ULL wd;
            wd = pack2(wv.x, wv.x);
            acc[c][0] = fma2(xp0[0], wd, acc[c][0]);
            acc[c][1] = fma2(xp1[0], wd, acc[c][1]);
            wd = pack2(wv.y, wv.y);
            acc[c][0] = fma2(xp0[1], wd, acc[c][0]);
            acc[c][1] = fma2(xp1[1], wd, acc[c][1]);
            wd = pack2(wv.z, wv.z);
            acc[c][0] = fma2(xp0[2], wd, acc[c][0]);
            acc[c][1] = fma2(xp1[2], wd, acc[c][1]);
            wd = pack2(wv.w, wv.w);
            acc[c][0] = fma2(xp0[3], wd, acc[c][0]);
            acc[c][1] = fma2(xp1[3], wd, acc[c][1]);
        }
    }
#pragma unroll
    for (int c = 0; c < 8; c++) {
#pragma unroll
        for (int m = 16; m >= 1; m >>= 1) {
            acc[c][0] = add2(acc[c][0], __shfl_down_sync(0xffffffffu, acc[c][0], m));
            acc[c][1] = add2(acc[c][1], __shfl_down_sync(0xffffffffu, acc[c][1], m));
        }
    }
    if (lane == 0) {
        int h = decode_dim(hptr);
        int w = decode_dim(wptr);
        int p = r0 >> 1;
#pragma unroll
        for (int c = 0; c < 8; c++) {
            float2 v0 = unpack2(acc[c][0]);   // rows r0, r0+1
            float2 v1 = unpack2(acc[c][1]);   // rows r0+2, r0+3
            float a0 = v0.x + pos_val((r0 + 0) & (N - 1), c, h, w);
            float a1 = v0.y + pos_val((r0 + 1) & (N - 1), c, h, w);
            float a2 = v1.x + pos_val((r0 + 2) & (N - 1), c, h, w);
            float a3 = v1.y + pos_val((r0 + 3) & (N - 1), c, h, w);
            g_kp[(size_t)(p + 0) * 8 + c] = make_float2(a0, a1);
            g_kp[(size_t)(p + 1) * 8 + c] = make_float2(a2, a3);
        }
    }
}

// ---------------------------------------------------------------------------
// Kernel 3: fused scores. Block = 32 q x 1024 k; thread owns 4 keys
// (2 f32x2 pairs, resident in 32 regs). 3 CTAs/SM for latency hiding.
// q row (144B) loaded as 9 LDG.128 (ulonglong2). Packed-fma2 epilogue.
// Streaming STG.128 (evict-first) for the 134MB output.
// ---------------------------------------------------------------------------
__global__ void __launch_bounds__(256, 3) scores_kernel(const float* __restrict__ sb,
                                                        float* __restrict__ out) {
    int b = blockIdx.z;
    int q0 = blockIdx.y * QT;
    int tid = threadIdx.x;

    // Resident keys: 2 pairs x 8 dims (flat offset computed once).
    ULL kreg[2][8];
    const ULL* kp = (const ULL*)g_kp
        + ((size_t)b * (N / 2) + (size_t)blockIdx.x * (KTB / 2) + (size_t)(tid * 2)) * 8;
#pragma unroll
    for (int pp = 0; pp < 2; pp++)
#pragma unroll
        for (int d = 0; d < 8; d++)
            kreg[pp][d] = kp[pp * 8 + d];

    float bias = sb[0];
    ULL biasd = pack2(bias, bias);
    const ulonglong2* qv2 = (const ulonglong2*)(g_qd + ((size_t)b * N + q0) * 18);
    float* orow = out + ((size_t)b * N + q0) * N
                + (size_t)blockIdx.x * KTB + (size_t)(tid * KPT);

#pragma unroll 2
    for (int q = 0; q < QT; q++) {
        ULL acc0[2], acc1[2];
        acc0[0] = acc0[1] = acc1[0] = acc1[1] = 0ull;
        // 9 x LDG.128: slots (0,1),(2,3),...,(16,17)
        ulonglong2 qa01 = qv2[0], qa23 = qv2[1], qa45 = qv2[2], qa67 = qv2[3];
        ulonglong2 qb01 = qv2[4], qb23 = qv2[5], qb45 = qv2[6], qb67 = qv2[7];
        ulonglong2 ww   = qv2[8];  // {w0 dup, w1 dup}
#pragma unroll
        for (int pp = 0; pp < 2; pp++) {
            acc0[pp] = fma2(kreg[pp][0], qa01.x, acc0[pp]);
            acc0[pp] = fma2(kreg[pp][1], qa01.y, acc0[pp]);
            acc0[pp] = fma2(kreg[pp][2], qa23.x, acc0[pp]);
            acc0[pp] = fma2(kreg[pp][3], qa23.y, acc0[pp]);
            acc0[pp] = fma2(kreg[pp][4], qa45.x, acc0[pp]);
            acc0[pp] = fma2(kreg[pp][5], qa45.y, acc0[pp]);
            acc0[pp] = fma2(kreg[pp][6], qa67.x, acc0[pp]);
            acc0[pp] = fma2(kreg[pp][7], qa67.y, acc0[pp]);
            acc1[pp] = fma2(kreg[pp][0], qb01.x, acc1[pp]);
            acc1[pp] = fma2(kreg[pp][1], qb01.y, acc1[pp]);
            acc1[pp] = fma2(kreg[pp][2], qb23.x, acc1[pp]);
            acc1[pp] = fma2(kreg[pp][3], qb23.y, acc1[pp]);
            acc1[pp] = fma2(kreg[pp][4], qb45.x, acc1[pp]);
            acc1[pp] = fma2(kreg[pp][5], qb45.y, acc1[pp]);
            acc1[pp] = fma2(kreg[pp][6], qb67.x, acc1[pp]);
            acc1[pp] = fma2(kreg[pp][7], qb67.y, acc1[pp]);
        }
        // Packed epilogue: relu lanes, then 2 fma2 per pair.
        float4 ov;
        {
            float2 a0 = unpack2(acc0[0]); float2 b0 = unpack2(acc1[0]);
            ULL r0 = pack2(fmaxf(a0.x, 0.f), fmaxf(a0.y, 0.f));
            ULL r1 = pack2(fmaxf(b0.x, 0.f), fmaxf(b0.y, 0.f));
            ULL o  = fma2(ww.y, r1, fma2(ww.x, r0, biasd));
            float2 of = unpack2(o);
            ov.x = of.x; ov.y = of.y;
        }
        {
            float2 a0 = unpack2(acc0[1]); float2 b0 = unpack2(acc1[1]);
            ULL r0 = pack2(fmaxf(a0.x, 0.f), fmaxf(a0.y, 0.f));
            ULL r1 = pack2(fmaxf(b0.x, 0.f), fmaxf(b0.y, 0.f));
            ULL o  = fma2(ww.y, r1, fma2(ww.x, r0, biasd));
            float2 of = unpack2(o);
            ov.z = of.x; ov.w = of.y;
        }
        __stcs((float4*)orow, ov);
        qv2 += 9;
        orow += N;
    }
}

// ---------------------------------------------------------------------------
extern "C" void kernel_launch(void* const* d_in, const int* in_sizes, int n_in,
                              void* d_out, int out_size) {
    const float* qt = (const float*)d_in[0];  // query_tokens (B,N,768)
    const float* kt = (const float*)d_in[1];  // key_tokens   (B,N,768)
    const float* Wq = (const float*)d_in[2];  // (768,18)
    const float* Wk = (const float*)d_in[3];  // (768,8)
    const float* sb = (const float*)d_in[4];  // spatial_bias (1,1,1)
    const void*  hp = d_in[5];                // height (scalar)
    const void*  wp = d_in[6];                // width  (scalar)
    float* out = (float*)d_out;               // (B,N,N) fp32
    (void)in_sizes; (void)n_in; (void)out_size;

    transpose_w_kernel<<<(DIM * CQ + 255) / 256, 256>>>(Wq, Wk);
    proj_q_kernel<<<(B * N) / 16, 256>>>(qt);
    proj_k_kernel<<<(B * N) / 32, 256>>>(kt, hp, wp);

    dim3 grid(N / KTB, N / QT, B);  // (4, 128, 2)
    scores_kernel<<<grid, TPB>>>(sb, out);
}

// round 15
// speedup vs baseline: 1.4692x; 1.2638x over previous
#include <cuda_runtime.h>

// ============================================================================
// LightningIndexer fused kernel for GB300 (sm_103a)  — Round 15
//
// out[b,q,k] = sum_h w[b,q,h] * relu(scale * dot(q[b,q,h,:], k[b,k,:])) + bias
//
// R14 post-mortem: KPT=4 doubled q-load traffic per output -> scores regressed
// 56->67.9us (L1 58%, issue 21.6%). This round: KPT=8 + SMEM q-tile staging
// (one cooperative load per block; in-loop q reads become broadcast LDS),
// LDG.128 key loads, packed-fma2 epilogue, __stcs stores.
// Prep kernels unchanged (measured 49 -> ~22.7us in R14).
// ============================================================================

#define ULL unsigned long long

__device__ __forceinline__ ULL pack2(float lo, float hi) {
    ULL r; asm("mov.b64 %0, {%1,%2};" : "=l"(r) : "f"(lo), "f"(hi)); return r;
}
__device__ __forceinline__ float2 unpack2(ULL v) {
    float2 f; asm("mov.b64 {%0,%1}, %2;" : "=f"(f.x), "=f"(f.y) : "l"(v)); return f;
}
__device__ __forceinline__ ULL fma2(ULL a, ULL b, ULL c) {
    ULL d; asm("fma.rn.f32x2 %0, %1, %2, %3;" : "=l"(d) : "l"(a), "l"(b), "l"(c)); return d;
}
__device__ __forceinline__ ULL add2(ULL a, ULL b) {
    ULL d; asm("add.rn.f32x2 %0, %1, %2;" : "=l"(d) : "l"(a), "l"(b)); return d;
}

constexpr int B   = 2;
constexpr int N   = 4096;
constexpr int DIM = 768;
constexpr int CQ  = 18;   // Wq output cols = H*(KD+1)
constexpr int CK  = 8;    // Wk output cols = KD
constexpr float SCALE = 0.35355339059327373f;  // 8^-0.5

// Scores tiling (KPT back to 8; q tile staged in SMEM)
constexpr int QT  = 32;           // queries per block
constexpr int TPB = 256;          // threads per block
constexpr int KPT = 8;            // keys per thread (4 f32x2 pairs)
constexpr int KTB = TPB * KPT;    // 2048 keys per block

// Scratch (device globals: no allocation allowed)
__device__ __align__(16) float  g_WqT[CQ * DIM];               // transposed Wq
__device__ __align__(16) float  g_WkT[CK * DIM];               // transposed Wk
__device__ __align__(16) float2 g_qd[(size_t)B * N * 18];      // duplicated q/w
__device__ __align__(16) float2 g_kp[(size_t)(B * N / 2) * 8]; // pair-packed k

// Robust positive-int scalar decode (int32 / int64-low-word / float32).
__device__ __forceinline__ int decode_dim(const void* p) {
    int vi = *(const int*)p;
    if (vi > 0 && vi < 100000) return vi;
    float vf = __int_as_float(vi);
    int r = (int)vf;
    return (r > 0 && r < 100000) ? r : 1;
}

// ---------------------------------------------------------------------------
// Kernel 0: transpose the tiny weight matrices (coalesced column reads later).
// ---------------------------------------------------------------------------
__global__ void transpose_w_kernel(const float* __restrict__ Wq,
                                   const float* __restrict__ Wk) {
    int t = blockIdx.x * blockDim.x + threadIdx.x;
    if (t < DIM * CQ) {
        int k = t / CQ, c = t % CQ;
        g_WqT[c * DIM + k] = Wq[t];
    }
    if (t < DIM * CK) {
        int k = t / CK, c = t % CK;
        g_WkT[c * DIM + k] = Wk[t];
    }
}

// ---------------------------------------------------------------------------
// Kernel 1: q/w projection (unchanged from R14; measured fast).
// ---------------------------------------------------------------------------
__global__ void __launch_bounds__(256, 3) proj_q_kernel(const float* __restrict__ tok) {
    int warp = threadIdx.x >> 5, lane = threadIdx.x & 31;
    int rg   = warp >> 1;          // row group 0..3
    int half = warp & 1;           // column half
    int r0   = blockIdx.x * 16 + rg * 4;
    int cbase = half * 9;

    const float4* x4 = (const float4*)(tok + (size_t)r0 * DIM);  // row stride 192
    const float4* w4 = (const float4*)g_WqT;                      // row stride 192

    ULL acc[9][2];
#pragma unroll
    for (int c = 0; c < 9; c++) { acc[c][0] = 0ull; acc[c][1] = 0ull; }

#pragma unroll
    for (int i = 0; i < 6; i++) {
        int kk = lane + i * 32;
        float4 xr0 = x4[0 * 192 + kk];
        float4 xr1 = x4[1 * 192 + kk];
        float4 xr2 = x4[2 * 192 + kk];
        float4 xr3 = x4[3 * 192 + kk];
        ULL xp0[4], xp1[4];
        xp0[0] = pack2(xr0.x, xr1.x); xp1[0] = pack2(xr2.x, xr3.x);
        xp0[1] = pack2(xr0.y, xr1.y); xp1[1] = pack2(xr2.y, xr3.y);
        xp0[2] = pack2(xr0.z, xr1.z); xp1[2] = pack2(xr2.z, xr3.z);
        xp0[3] = pack2(xr0.w, xr1.w); xp1[3] = pack2(xr2.w, xr3.w);
#pragma unroll
        for (int c = 0; c < 9; c++) {
            float4 wv = w4[(size_t)(cbase + c) * 192 + kk];
            ULL wd;
            wd = pack2(wv.x, wv.x);
            acc[c][0] = fma2(xp0[0], wd, acc[c][0]);
            acc[c][1] = fma2(xp1[0], wd, acc[c][1]);
            wd = pack2(wv.y, wv.y);
            acc[c][0] = fma2(xp0[1], wd, acc[c][0]);
            acc[c][1] = fma2(xp1[1], wd, acc[c][1]);
            wd = pack2(wv.z, wv.z);
            acc[c][0] = fma2(xp0[2], wd, acc[c][0]);
            acc[c][1] = fma2(xp1[2], wd, acc[c][1]);
            wd = pack2(wv.w, wv.w);
            acc[c][0] = fma2(xp0[3], wd, acc[c][0]);
            acc[c][1] = fma2(xp1[3], wd, acc[c][1]);
        }
    }
#pragma unroll
    for (int c = 0; c < 9; c++) {
#pragma unroll
        for (int m = 16; m >= 1; m >>= 1) {
            acc[c][0] = add2(acc[c][0], __shfl_down_sync(0xffffffffu, acc[c][0], m));
            acc[c][1] = add2(acc[c][1], __shfl_down_sync(0xffffffffu, acc[c][1], m));
        }
    }
    if (lane == 0) {
#pragma unroll
        for (int c = 0; c < 9; c++) {
            int cc = cbase + c;
            int slot; float mul;
            if (cc < 8)       { slot = cc;     mul = SCALE; }
            else if (cc == 8) { slot = 16;     mul = 1.0f; }
            else if (cc < 17) { slot = cc - 1; mul = SCALE; }
            else              { slot = 17;     mul = 1.0f; }
            float2 v0 = unpack2(acc[c][0]);
            float2 v1 = unpack2(acc[c][1]);
            float a = v0.x * mul, b = v0.y * mul, e = v1.x * mul, d = v1.y * mul;
            g_qd[(size_t)(r0 + 0) * 18 + slot] = make_float2(a, a);
            g_qd[(size_t)(r0 + 1) * 18 + slot] = make_float2(b, b);
            g_qd[(size_t)(r0 + 2) * 18 + slot] = make_float2(e, e);
            g_qd[(size_t)(r0 + 3) * 18 + slot] = make_float2(d, d);
        }
    }
}

// ---------------------------------------------------------------------------
// 2D sinusoidal position embedding value for (token n, dim d).
// ---------------------------------------------------------------------------
__device__ __forceinline__ float pos_val(int n, int d, int h, int w) {
    int dd = d & 3;
    float t, sc;
    if (d < 4) {
        int y = n / w;
        int hm1 = (h - 1 > 1) ? (h - 1) : 1;
        t = (float)y / (float)hm1; sc = (float)h;
    } else {
        int xx = n % w;
        int wm1 = (w - 1 > 1) ? (w - 1) : 1;
        t = (float)xx / (float)wm1; sc = (float)w;
    }
    float fr = (dd < 2) ? 1.0f : expf(-0.5f * logf(10000.0f));
    float a = (t * fr) * sc;
    return (dd & 1) ? cosf(a) : sinf(a);
}

// ---------------------------------------------------------------------------
// Kernel 2: k projection + pos-emb (unchanged from R14; measured fast).
// ---------------------------------------------------------------------------
__global__ void __launch_bounds__(256, 3) proj_k_kernel(const float* __restrict__ tok,
                                                        const void* __restrict__ hptr,
                                                        const void* __restrict__ wptr) {
    int warp = threadIdx.x >> 5, lane = threadIdx.x & 31;
    int r0 = blockIdx.x * 32 + warp * 4;

    const float4* x4 = (const float4*)(tok + (size_t)r0 * DIM);
    const float4* w4 = (const float4*)g_WkT;

    ULL acc[8][2];
#pragma unroll
    for (int c = 0; c < 8; c++) { acc[c][0] = 0ull; acc[c][1] = 0ull; }

#pragma unroll
    for (int i = 0; i < 6; i++) {
        int kk = lane + i * 32;
        float4 xr0 = x4[0 * 192 + kk];
        float4 xr1 = x4[1 * 192 + kk];
        float4 xr2 = x4[2 * 192 + kk];
        float4 xr3 = x4[3 * 192 + kk];
        ULL xp0[4], xp1[4];
        xp0[0] = pack2(xr0.x, xr1.x); xp1[0] = pack2(xr2.x, xr3.x);
        xp0[1] = pack2(xr0.y, xr1.y); xp1[1] = pack2(xr2.y, xr3.y);
        xp0[2] = pack2(xr0.z, xr1.z); xp1[2] = pack2(xr2.z, xr3.z);
        xp0[3] = pack2(xr0.w, xr1.w); xp1[3] = pack2(xr2.w, xr3.w);
#pragma unroll
        for (int c = 0; c < 8; c++) {
            float4 wv = w4[(size_t)c * 192 + kk];
            ULL wd;
            wd = pack2(wv.x, wv.x);
            acc[c][0] = fma2(xp0[0], wd, acc[c][0]);
            acc[c][1] = fma2(xp1[0], wd, acc[c][1]);
            wd = pack2(wv.y, wv.y);
            acc[c][0] = fma2(xp0[1], wd, acc[c][0]);
            acc[c][1] = fma2(xp1[1], wd, acc[c][1]);
            wd = pack2(wv.z, wv.z);
            acc[c][0] = fma2(xp0[2], wd, acc[c][0]);
            acc[c][1] = fma2(xp1[2], wd, acc[c][1]);
            wd = pack2(wv.w, wv.w);
            acc[c][0] = fma2(xp0[3], wd, acc[c][0]);
            acc[c][1] = fma2(xp1[3], wd, acc[c][1]);
        }
    }
#pragma unroll
    for (int c = 0; c < 8; c++) {
#pragma unroll
        for (int m = 16; m >= 1; m >>= 1) {
            acc[c][0] = add2(acc[c][0], __shfl_down_sync(0xffffffffu, acc[c][0], m));
            acc[c][1] = add2(acc[c][1], __shfl_down_sync(0xffffffffu, acc[c][1], m));
        }
    }
    if (lane == 0) {
        int h = decode_dim(hptr);
        int w = decode_dim(wptr);
        int p = r0 >> 1;
#pragma unroll
        for (int c = 0; c < 8; c++) {
            float2 v0 = unpack2(acc[c][0]);   // rows r0, r0+1
            float2 v1 = unpack2(acc[c][1]);   // rows r0+2, r0+3
            float a0 = v0.x + pos_val((r0 + 0) & (N - 1), c, h, w);
            float a1 = v0.y + pos_val((r0 + 1) & (N - 1), c, h, w);
            float a2 = v1.x + pos_val((r0 + 2) & (N - 1), c, h, w);
            float a3 = v1.y + pos_val((r0 + 3) & (N - 1), c, h, w);
            g_kp[(size_t)(p + 0) * 8 + c] = make_float2(a0, a1);
            g_kp[(size_t)(p + 1) * 8 + c] = make_float2(a2, a3);
        }
    }
}

// ---------------------------------------------------------------------------
// Kernel 3: fused scores v3. Block = 32 q x 2048 k; thread owns 8 keys
// (4 f32x2 pairs in 64 regs, loaded via 16 LDG.128). The 32-row q-tile
// (4.6KB) is staged in SMEM once per block; in-loop q reads are 9 broadcast
// LDS.128 per q-iter (no global latency exposure in the mainloop).
// Packed-fma2 epilogue; __stcs streaming stores.
// ---------------------------------------------------------------------------
__global__ void __launch_bounds__(256, 2) scores_kernel(const float* __restrict__ sb,
                                                        float* __restrict__ out) {
    __shared__ __align__(16) ULL s_q[QT * 18];  // 4608 B

    int b = blockIdx.z;
    int q0 = blockIdx.y * QT;
    int tid = threadIdx.x;

    // Stage q tile (32 rows x 18 packed slots).
    {
        const ULL* qsrc = (const ULL*)(g_qd + ((size_t)b * N + q0) * 18);
        for (int i = tid; i < QT * 18; i += TPB) s_q[i] = qsrc[i];
    }

    // Resident keys: 4 pairs x 8 dims via 16 LDG.128 (256B contiguous).
    ULL kreg[4][8];
    {
        const ulonglong2* kp2 = (const ulonglong2*)((const ULL*)g_kp
            + ((size_t)b * (N / 2) + (size_t)blockIdx.x * (KTB / 2)
               + (size_t)(tid * 4)) * 8);
#pragma unroll
        for (int pp = 0; pp < 4; pp++)
#pragma unroll
            for (int d2 = 0; d2 < 4; d2++) {
                ulonglong2 v = kp2[pp * 4 + d2];
                kreg[pp][2 * d2]     = v.x;
                kreg[pp][2 * d2 + 1] = v.y;
            }
    }

    float bias = sb[0];
    ULL biasd = pack2(bias, bias);
    __syncthreads();

    float* orow = out + ((size_t)b * N + q0) * N
                + (size_t)blockIdx.x * KTB + (size_t)(tid * KPT);

    for (int q = 0; q < QT; q++) {
        const ULL* qq = s_q + q * 18;
        ULL acc0[4], acc1[4];
#pragma unroll
        for (int pp = 0; pp < 4; pp++) { acc0[pp] = 0ull; acc1[pp] = 0ull; }
#pragma unroll
        for (int d = 0; d < 8; d++) {
            ULL qa = qq[d];      // head 0, dim d (broadcast LDS)
            ULL qb = qq[8 + d];  // head 1
#pragma unroll
            for (int pp = 0; pp < 4; pp++) {
                acc0[pp] = fma2(kreg[pp][d], qa, acc0[pp]);
                acc1[pp] = fma2(kreg[pp][d], qb, acc1[pp]);
            }
        }
        ULL w0d = qq[16];  // {w0, w0}
        ULL w1d = qq[17];  // {w1, w1}
        float o[8];
#pragma unroll
        for (int pp = 0; pp < 4; pp++) {
            float2 a0 = unpack2(acc0[pp]);
            float2 b0 = unpack2(acc1[pp]);
            ULL r0 = pack2(fmaxf(a0.x, 0.f), fmaxf(a0.y, 0.f));
            ULL r1 = pack2(fmaxf(b0.x, 0.f), fmaxf(b0.y, 0.f));
            ULL oo = fma2(w1d, r1, fma2(w0d, r0, biasd));
            float2 of = unpack2(oo);
            o[2 * pp]     = of.x;
            o[2 * pp + 1] = of.y;
        }
        __stcs((float4*)orow,     make_float4(o[0], o[1], o[2], o[3]));
        __stcs((float4*)orow + 1, make_float4(o[4], o[5], o[6], o[7]));
        orow += N;
    }
}

// ---------------------------------------------------------------------------
extern "C" void kernel_launch(void* const* d_in, const int* in_sizes, int n_in,
                              void* d_out, int out_size) {
    const float* qt = (const float*)d_in[0];  // query_tokens (B,N,768)
    const float* kt = (const float*)d_in[1];  // key_tokens   (B,N,768)
    const float* Wq = (const float*)d_in[2];  // (768,18)
    const float* Wk = (const float*)d_in[3];  // (768,8)
    const float* sb = (const float*)d_in[4];  // spatial_bias (1,1,1)
    const void*  hp = d_in[5];                // height (scalar)
    const void*  wp = d_in[6];                // width  (scalar)
    float* out = (float*)d_out;               // (B,N,N) fp32
    (void)in_sizes; (void)n_in; (void)out_size;

    transpose_w_kernel<<<(DIM * CQ + 255) / 256, 256>>>(Wq, Wk);
    proj_q_kernel<<<(B * N) / 16, 256>>>(qt);
    proj_k_kernel<<<(B * N) / 32, 256>>>(kt, hp, wp);

    dim3 grid(N / KTB, N / QT, B);  // (2, 128, 2)
    scores_kernel<<<grid, TPB>>>(sb, out);
}

// round 17
// speedup vs baseline: 1.5110x; 1.0285x over previous
#include <cuda_runtime.h>

// ============================================================================
// LightningIndexer fused kernel for GB300 (sm_103a)  — Round 17 (R16 design,
// resubmitted unchanged; R16 died to broker GPUAcquisitionTimeout before
// execution).
//
// out[b,q,k] = sum_h w[b,q,h] * relu(scale * dot(q[b,q,h,:], k[b,k,:])) + bias
//
// R15: scores 40.1us (issue 36%, fma 38%, 126 regs, 2 CTA/SM); prep ~22.7us.
// This design:
//  - packed epilogue via relu(s)=(s+|s|)/2 with w/2 folded into projection:
//    kills 16 FMNMX + ~32 MOVs per iter; outputs stored packed (double2).
//  - proj_q and proj_k fused into ONE launch (block-range dispatch) so the
//    two projections overlap.
// ============================================================================

#define ULL unsigned long long

__device__ __forceinline__ ULL pack2(float lo, float hi) {
    ULL r; asm("mov.b64 %0, {%1,%2};" : "=l"(r) : "f"(lo), "f"(hi)); return r;
}
__device__ __forceinline__ float2 unpack2(ULL v) {
    float2 f; asm("mov.b64 {%0,%1}, %2;" : "=f"(f.x), "=f"(f.y) : "l"(v)); return f;
}
__device__ __forceinline__ ULL fma2(ULL a, ULL b, ULL c) {
    ULL d; asm("fma.rn.f32x2 %0, %1, %2, %3;" : "=l"(d) : "l"(a), "l"(b), "l"(c)); return d;
}
__device__ __forceinline__ ULL add2(ULL a, ULL b) {
    ULL d; asm("add.rn.f32x2 %0, %1, %2;" : "=l"(d) : "l"(a), "l"(b)); return d;
}

constexpr int B   = 2;
constexpr int N   = 4096;
constexpr int DIM = 768;
constexpr int CQ  = 18;   // Wq output cols = H*(KD+1)
constexpr int CK  = 8;    // Wk output cols = KD
constexpr float SCALE = 0.35355339059327373f;  // 8^-0.5

// Scores tiling
constexpr int QT  = 32;           // queries per block
constexpr int TPB = 256;          // threads per block
constexpr int KPT = 8;            // keys per thread (4 f32x2 pairs)
constexpr int KTB = TPB * KPT;    // 2048 keys per block

// Fused projection kernel block split
constexpr int NQB = (B * N) / 16; // 512 proj_q blocks (16 rows each)
constexpr int NKB = (B * N) / 32; // 256 proj_k blocks (32 rows each)

// Scratch (device globals: no allocation allowed)
__device__ __align__(16) float  g_WqT[CQ * DIM];               // transposed Wq
__device__ __align__(16) float  g_WkT[CK * DIM];               // transposed Wk
__device__ __align__(16) float2 g_qd[(size_t)B * N * 18];      // duplicated q (+w/2)
__device__ __align__(16) float2 g_kp[(size_t)(B * N / 2) * 8]; // pair-packed k

// Robust positive-int scalar decode (int32 / int64-low-word / float32).
__device__ __forceinline__ int decode_dim(const void* p) {
    int vi = *(const int*)p;
    if (vi > 0 && vi < 100000) return vi;
    float vf = __int_as_float(vi);
    int r = (int)vf;
    return (r > 0 && r < 100000) ? r : 1;
}

// ---------------------------------------------------------------------------
// Kernel 0: transpose the tiny weight matrices.
// ---------------------------------------------------------------------------
__global__ void transpose_w_kernel(const float* __restrict__ Wq,
                                   const float* __restrict__ Wk) {
    int t = blockIdx.x * blockDim.x + threadIdx.x;
    if (t < DIM * CQ) {
        int k = t / CQ, c = t % CQ;
        g_WqT[c * DIM + k] = Wq[t];
    }
    if (t < DIM * CK) {
        int k = t / CK, c = t % CK;
        g_WkT[c * DIM + k] = Wk[t];
    }
}

// ---------------------------------------------------------------------------
// 2D sinusoidal position embedding value for (token n, dim d).
// ---------------------------------------------------------------------------
__device__ __forceinline__ float pos_val(int n, int d, int h, int w) {
    int dd = d & 3;
    float t, sc;
    if (d < 4) {
        int y = n / w;
        int hm1 = (h - 1 > 1) ? (h - 1) : 1;
        t = (float)y / (float)hm1; sc = (float)h;
    } else {
        int xx = n % w;
        int wm1 = (w - 1 > 1) ? (w - 1) : 1;
        t = (float)xx / (float)wm1; sc = (float)w;
    }
    float fr = (dd < 2) ? 1.0f : expf(-0.5f * logf(10000.0f));
    float a = (t * fr) * sc;
    return (dd & 1) ? cosf(a) : sinf(a);
}

// ---------------------------------------------------------------------------
// proj_q body: warp = 4 rows x 9 cols; float4 loads; f32x2 row-pairs.
// Slot map: c'<8 -> slot c' (*SCALE); c'==8 -> slot 16 (*0.5);
//           c'<17 -> slot c'-1 (*SCALE); c'==17 -> slot 17 (*0.5).
// w stored PRE-HALVED for the relu(s)=(s+|s|)/2 epilogue.
// ---------------------------------------------------------------------------
__device__ __forceinline__ void proj_q_body(const float* __restrict__ tok, int bid) {
    int warp = threadIdx.x >> 5, lane = threadIdx.x & 31;
    int rg   = warp >> 1;
    int half = warp & 1;
    int r0   = bid * 16 + rg * 4;
    int cbase = half * 9;

    const float4* x4 = (const float4*)(tok + (size_t)r0 * DIM);
    const float4* w4 = (const float4*)g_WqT;

    ULL acc[9][2];
#pragma unroll
    for (int c = 0; c < 9; c++) { acc[c][0] = 0ull; acc[c][1] = 0ull; }

#pragma unroll
    for (int i = 0; i < 6; i++) {
        int kk = lane + i * 32;
        float4 xr0 = x4[0 * 192 + kk];
        float4 xr1 = x4[1 * 192 + kk];
        float4 xr2 = x4[2 * 192 + kk];
        float4 xr3 = x4[3 * 192 + kk];
        ULL xp0[4], xp1[4];
        xp0[0] = pack2(xr0.x, xr1.x); xp1[0] = pack2(xr2.x, xr3.x);
        xp0[1] = pack2(xr0.y, xr1.y); xp1[1] = pack2(xr2.y, xr3.y);
        xp0[2] = pack2(xr0.z, xr1.z); xp1[2] = pack2(xr2.z, xr3.z);
        xp0[3] = pack2(xr0.w, xr1.w); xp1[3] = pack2(xr2.w, xr3.w);
#pragma unroll
        for (int c = 0; c < 9; c++) {
            float4 wv = w4[(size_t)(cbase + c) * 192 + kk];
            ULL wd;
            wd = pack2(wv.x, wv.x);
            acc[c][0] = fma2(xp0[0], wd, acc[c][0]);
            acc[c][1] = fma2(xp1[0], wd, acc[c][1]);
            wd = pack2(wv.y, wv.y);
            acc[c][0] = fma2(xp0[1], wd, acc[c][0]);
            acc[c][1] = fma2(xp1[1], wd, acc[c][1]);
            wd = pack2(wv.z, wv.z);
            acc[c][0] = fma2(xp0[2], wd, acc[c][0]);
            acc[c][1] = fma2(xp1[2], wd, acc[c][1]);
            wd = pack2(wv.w, wv.w);
            acc[c][0] = fma2(xp0[3], wd, acc[c][0]);
            acc[c][1] = fma2(xp1[3], wd, acc[c][1]);
        }
    }
#pragma unroll
    for (int c = 0; c < 9; c++) {
#pragma unroll
        for (int m = 16; m >= 1; m >>= 1) {
            acc[c][0] = add2(acc[c][0], __shfl_down_sync(0xffffffffu, acc[c][0], m));
            acc[c][1] = add2(acc[c][1], __shfl_down_sync(0xffffffffu, acc[c][1], m));
        }
    }
    if (lane == 0) {
#pragma unroll
        for (int c = 0; c < 9; c++) {
            int cc = cbase + c;
            int slot; float mul;
            if (cc < 8)       { slot = cc;     mul = SCALE; }
            else if (cc == 8) { slot = 16;     mul = 0.5f; }
            else if (cc < 17) { slot = cc - 1; mul = SCALE; }
            else              { slot = 17;     mul = 0.5f; }
            float2 v0 = unpack2(acc[c][0]);
            float2 v1 = unpack2(acc[c][1]);
            float a = v0.x * mul, b = v0.y * mul, e = v1.x * mul, d = v1.y * mul;
            g_qd[(size_t)(r0 + 0) * 18 + slot] = make_float2(a, a);
            g_qd[(size_t)(r0 + 1) * 18 + slot] = make_float2(b, b);
            g_qd[(size_t)(r0 + 2) * 18 + slot] = make_float2(e, e);
            g_qd[(size_t)(r0 + 3) * 18 + slot] = make_float2(d, d);
        }
    }
}

// ---------------------------------------------------------------------------
// proj_k body: warp = 4 rows x 8 cols; float4 loads; pair-packed output.
// ---------------------------------------------------------------------------
__device__ __forceinline__ void proj_k_body(const float* __restrict__ tok, int bid,
                                            const void* hptr, const void* wptr) {
    int warp = threadIdx.x >> 5, lane = threadIdx.x & 31;
    int r0 = bid * 32 + warp * 4;

    const float4* x4 = (const float4*)(tok + (size_t)r0 * DIM);
    const float4* w4 = (const float4*)g_WkT;

    ULL acc[8][2];
#pragma unroll
    for (int c = 0; c < 8; c++) { acc[c][0] = 0ull; acc[c][1] = 0ull; }

#pragma unroll
    for (int i = 0; i < 6; i++) {
        int kk = lane + i * 32;
        float4 xr0 = x4[0 * 192 + kk];
        float4 xr1 = x4[1 * 192 + kk];
        float4 xr2 = x4[2 * 192 + kk];
        float4 xr3 = x4[3 * 192 + kk];
        ULL xp0[4], xp1[4];
        xp0[0] = pack2(xr0.x, xr1.x); xp1[0] = pack2(xr2.x, xr3.x);
        xp0[1] = pack2(xr0.y, xr1.y); xp1[1] = pack2(xr2.y, xr3.y);
        xp0[2] = pack2(xr0.z, xr1.z); xp1[2] = pack2(xr2.z, xr3.z);
        xp0[3] = pack2(xr0.w, xr1.w); xp1[3] = pack2(xr2.w, xr3.w);
#pragma unroll
        for (int c = 0; c < 8; c++) {
            float4 wv = w4[(size_t)c * 192 + kk];
            ULL wd;
            wd = pack2(wv.x, wv.x);
            acc[c][0] = fma2(xp0[0], wd, acc[c][0]);
            acc[c][1] = fma2(xp1[0], wd, acc[c][1]);
            wd = pack2(wv.y, wv.y);
            acc[c][0] = fma2(xp0[1], wd, acc[c][0]);
            acc[c][1] = fma2(xp1[1], wd, acc[c][1]);
            wd = pack2(wv.z, wv.z);
            acc[c][0] = fma2(xp0[2], wd, acc[c][0]);
            acc[c][1] = fma2(xp1[2], wd, acc[c][1]);
            wd = pack2(wv.w, wv.w);
            acc[c][0] = fma2(xp0[3], wd, acc[c][0]);
            acc[c][1] = fma2(xp1[3], wd, acc[c][1]);
        }
    }
#pragma unroll
    for (int c = 0; c < 8; c++) {
#pragma unroll
        for (int m = 16; m >= 1; m >>= 1) {
            acc[c][0] = add2(acc[c][0], __shfl_down_sync(0xffffffffu, acc[c][0], m));
            acc[c][1] = add2(acc[c][1], __shfl_down_sync(0xffffffffu, acc[c][1], m));
        }
    }
    if (lane == 0) {
        int h = decode_dim(hptr);
        int w = decode_dim(wptr);
        int p = r0 >> 1;
#pragma unroll
        for (int c = 0; c < 8; c++) {
            float2 v0 = unpack2(acc[c][0]);   // rows r0, r0+1
            float2 v1 = unpack2(acc[c][1]);   // rows r0+2, r0+3
            float a0 = v0.x + pos_val((r0 + 0) & (N - 1), c, h, w);
            float a1 = v0.y + pos_val((r0 + 1) & (N - 1), c, h, w);
            float a2 = v1.x + pos_val((r0 + 2) & (N - 1), c, h, w);
            float a3 = v1.y + pos_val((r0 + 3) & (N - 1), c, h, w);
            g_kp[(size_t)(p + 0) * 8 + c] = make_float2(a0, a1);
            g_kp[(size_t)(p + 1) * 8 + c] = make_float2(a2, a3);
        }
    }
}

// ---------------------------------------------------------------------------
// Kernel 1: fused q/k projections (block-range dispatch; the two projections
// overlap on the chip instead of serializing across launches).
// ---------------------------------------------------------------------------
__global__ void __launch_bounds__(256, 3) proj_qk_kernel(const float* __restrict__ qt,
                                                         const float* __restrict__ kt,
                                                         const void* __restrict__ hptr,
                                                         const void* __restrict__ wptr) {
    if (blockIdx.x < NQB) {
        proj_q_body(qt, blockIdx.x);
    } else {
        proj_k_body(kt, blockIdx.x - NQB, hptr, wptr);
    }
}

// ---------------------------------------------------------------------------
// Kernel 2: fused scores v4. Block = 32 q x 2048 k; thread owns 8 keys
// (4 f32x2 pairs, 16 LDG.128). 32-row q-tile staged in SMEM (4.6KB).
// Epilogue fully packed: out = bias + (w0/2)(s0+|s0|) + (w1/2)(s1+|s1|)
//  = 2 LOP-AND (ALU) + 4 chained fma2 per pair; stores as packed double2.
// ---------------------------------------------------------------------------
__global__ void __launch_bounds__(256, 2) scores_kernel(const float* __restrict__ sb,
                                                        float* __restrict__ out) {
    __shared__ __align__(16) ULL s_q[QT * 18];  // 4608 B

    int b = blockIdx.z;
    int q0 = blockIdx.y * QT;
    int tid = threadIdx.x;

    // Stage q tile (32 rows x 18 packed slots).
    {
        const ULL* qsrc = (const ULL*)(g_qd + ((size_t)b * N + q0) * 18);
        for (int i = tid; i < QT * 18; i += TPB) s_q[i] = qsrc[i];
    }

    // Resident keys: 4 pairs x 8 dims via 16 LDG.128 (256B contiguous).
    ULL kreg[4][8];
    {
        const ulonglong2* kp2 = (const ulonglong2*)((const ULL*)g_kp
            + ((size_t)b * (N / 2) + (size_t)blockIdx.x * (KTB / 2)
               + (size_t)(tid * 4)) * 8);
#pragma unroll
        for (int pp = 0; pp < 4; pp++)
#pragma unroll
            for (int d2 = 0; d2 < 4; d2++) {
                ulonglong2 v = kp2[pp * 4 + d2];
                kreg[pp][2 * d2]     = v.x;
                kreg[pp][2 * d2 + 1] = v.y;
            }
    }

    float bias = sb[0];
    ULL biasd = pack2(bias, bias);
    __syncthreads();

    float* orow = out + ((size_t)b * N + q0) * N
                + (size_t)blockIdx.x * KTB + (size_t)(tid * KPT);

    const ULL ABSM = 0x7FFFFFFF7FFFFFFFull;

    for (int q = 0; q < QT; q++) {
        const ULL* qq = s_q + q * 18;
        ULL acc0[4], acc1[4];
#pragma unroll
        for (int pp = 0; pp < 4; pp++) { acc0[pp] = 0ull; acc1[pp] = 0ull; }
#pragma unroll
        for (int d = 0; d < 8; d++) {
            ULL qa = qq[d];      // head 0, dim d (broadcast LDS)
            ULL qb = qq[8 + d];  // head 1
#pragma unroll
            for (int pp = 0; pp < 4; pp++) {
                acc0[pp] = fma2(kreg[pp][d], qa, acc0[pp]);
                acc1[pp] = fma2(kreg[pp][d], qb, acc1[pp]);
            }
        }
        ULL w0h = qq[16];  // {w0/2, w0/2}
        ULL w1h = qq[17];  // {w1/2, w1/2}
        ULL oo[4];
#pragma unroll
        for (int pp = 0; pp < 4; pp++) {
            ULL s0 = acc0[pp], s1 = acc1[pp];
            ULL a0 = s0 & ABSM;
            ULL a1 = s1 & ABSM;
            oo[pp] = fma2(w1h, a1, fma2(w1h, s1,
                      fma2(w0h, a0, fma2(w0h, s0, biasd))));
        }
        double2 d0, d1;
        d0.x = __longlong_as_double((long long)oo[0]);
        d0.y = __longlong_as_double((long long)oo[1]);
        d1.x = __longlong_as_double((long long)oo[2]);
        d1.y = __longlong_as_double((long long)oo[3]);
        __stcs((double2*)orow, d0);
        __stcs((double2*)orow + 1, d1);
        orow += N;
    }
}

// ---------------------------------------------------------------------------
extern "C" void kernel_launch(void* const* d_in, const int* in_sizes, int n_in,
                              void* d_out, int out_size) {
    const float* qt = (const float*)d_in[0];  // query_tokens (B,N,768)
    const float* kt = (const float*)d_in[1];  // key_tokens   (B,N,768)
    const float* Wq = (const float*)d_in[2];  // (768,18)
    const float* Wk = (const float*)d_in[3];  // (768,8)
    const float* sb = (const float*)d_in[4];  // spatial_bias (1,1,1)
    const void*  hp = d_in[5];                // height (scalar)
    const void*  wp = d_in[6];                // width  (scalar)
    float* out = (float*)d_out;               // (B,N,N) fp32
    (void)in_sizes; (void)n_in; (void)out_size;

    transpose_w_kernel<<<(DIM * CQ + 255) / 256, 256>>>(Wq, Wk);
    proj_qk_kernel<<<NQB + NKB, 256>>>(qt, kt, hp, wp);

    dim3 grid(N / KTB, N / QT, B);  // (2, 128, 2)
    scores_kernel<<<grid, TPB>>>(sb, out);
}